// round 3
// baseline (speedup 1.0000x reference)
#include <cuda_runtime.h>
#include <cstdint>

#define D_MODEL 1024
#define NHEAD   16
#define DKH     64
#define BATCH   8
#define SEQ     1024
#define MROWS   (BATCH*SEQ)                   // 8192
#define OUT_ELEMS  (MROWS*D_MODEL)            // 8388608
#define ATTN_ELEMS (BATCH*NHEAD*SEQ*SEQ)      // 134217728

// ---------------- scratch (no cudaMalloc allowed) ----------------
__device__ float g_q  [MROWS*D_MODEL];
__device__ float g_k  [MROWS*D_MODEL];
__device__ float g_v  [MROWS*D_MODEL];
__device__ float g_ctx[MROWS*D_MODEL];

// ---------------- helpers ----------------
__device__ __forceinline__ unsigned f2tf32(float f){
  unsigned r; asm("cvt.rna.tf32.f32 %0, %1;" : "=r"(r) : "f"(f)); return r;
}
__device__ __forceinline__ uint32_t smem_u32(const void* p){
  return (uint32_t)__cvta_generic_to_shared(p);
}
__device__ __forceinline__ void ldsm4(unsigned &r0, unsigned &r1, unsigned &r2, unsigned &r3, uint32_t a){
  asm volatile("ldmatrix.sync.aligned.m8n8.x4.shared.b16 {%0,%1,%2,%3}, [%4];"
    : "=r"(r0),"=r"(r1),"=r"(r2),"=r"(r3) : "r"(a));
}
__device__ __forceinline__ void mma_tf32(float &d0,float &d1,float &d2,float &d3,
    unsigned a0,unsigned a1,unsigned a2,unsigned a3, unsigned b0,unsigned b1){
  asm volatile("mma.sync.aligned.m16n8k8.row.col.f32.tf32.tf32.f32 "
    "{%0,%1,%2,%3}, {%4,%5,%6,%7}, {%8,%9}, {%0,%1,%2,%3};"
    : "+f"(d0),"+f"(d1),"+f"(d2),"+f"(d3)
    : "r"(a0),"r"(a1),"r"(a2),"r"(a3),"r"(b0),"r"(b1));
}
// FFMA-only exp (avoids the MUFU rt=8 bottleneck: 134M exps).
// Valid for x <= 0 (post max-subtraction); rel err ~2e-6.
__device__ __forceinline__ float fast_exp(float x){
  x = fmaxf(x, -80.f);
  float z  = fmaf(x, 1.4426950408889634f, 12582912.f); // round-to-int via magic
  int   n  = __float_as_int(z) - 0x4B400000;
  float fn = z - 12582912.f;
  float t  = fmaf(x, 1.4426950408889634f, -fn);        // frac in [-0.5, 0.5]
  float u  = t * 0.6931471805599453f;                  // [-0.347, 0.347]
  float p  = fmaf(u, 0.0083333333f, 0.0416666667f);
  p = fmaf(u, p, 0.1666666667f);
  p = fmaf(u, p, 0.5f);
  p = fmaf(u, p, 1.0f);
  p = fmaf(u, p, 1.0f);
  return __int_as_float((n + 127) << 23) * p;
}

// ================= TF32 GEMM:  C[M,N] = A[M,K] @ W[N,K]^T + bias[N] =================
#define GBM 128
#define GBN 128
#define GBK 32
#define GPAD 36                                   // stride%32==4 -> conflict-free ldsm; %4==0 -> STS.128 ok
#define GEMM_SMEM_BYTES (4*GBM*GPAD*4)            // 73728 B: A(2 buf) + W(2 buf)

__global__ __launch_bounds__(256)
void gemm_tf32_kernel(const float* __restrict__ A, const float* __restrict__ W,
                      const float* __restrict__ bias, float* __restrict__ C,
                      int M, int N, int K)
{
  extern __shared__ float sm[];
  float* As = sm;                   // [2][128][36]
  float* Ws = sm + 2*GBM*GPAD;      // [2][128][36]  rows = n
  const int tid = threadIdx.x, lane = tid & 31, wid = tid >> 5;
  const int wr = wid & 3, wc = wid >> 2;          // 4x2 warp grid, warp tile 32x64
  const int bm0 = blockIdx.y * GBM, bn0 = blockIdx.x * GBN;
  const int qg = lane >> 3, lr = lane & 7;
  const int aRow = wr*32 + (qg & 1)*8 + lr;       // + mt*16
  const int aCol = (qg >> 1)*4;
  const int bRow = wc*64 + (qg >> 1)*8 + lr;      // + np*16
  const int bCol = (qg & 1)*4;

  float acc[2][8][4];
  #pragma unroll
  for (int mt = 0; mt < 2; mt++)
    #pragma unroll
    for (int nt = 0; nt < 8; nt++)
      #pragma unroll
      for (int j = 0; j < 4; j++) acc[mt][nt][j] = 0.f;

  float4 ra[4], rw[4];
  const int nT = K / GBK;

  #pragma unroll
  for (int i = 0; i < 4; i++) {                   // prologue LDG tile 0
    int f4 = i*256 + tid; int r = f4 >> 3; int c = (f4 & 7) << 2;
    ra[i] = *(const float4*)(A + (size_t)(bm0 + r)*K + c);
    rw[i] = *(const float4*)(W + (size_t)(bn0 + r)*K + c);
  }

  for (int t = 0; t < nT; t++) {
    float* as = As + (t & 1)*GBM*GPAD;
    float* ws = Ws + (t & 1)*GBM*GPAD;
    #pragma unroll
    for (int i = 0; i < 4; i++) {                 // fused fp32->tf32 + STS.128
      int f4 = i*256 + tid; int r = f4 >> 3; int c = (f4 & 7) << 2;
      uint4 ua; ua.x=f2tf32(ra[i].x); ua.y=f2tf32(ra[i].y); ua.z=f2tf32(ra[i].z); ua.w=f2tf32(ra[i].w);
      uint4 uw; uw.x=f2tf32(rw[i].x); uw.y=f2tf32(rw[i].y); uw.z=f2tf32(rw[i].z); uw.w=f2tf32(rw[i].w);
      *(uint4*)(as + r*GPAD + c) = ua;
      *(uint4*)(ws + r*GPAD + c) = uw;
    }
    __syncthreads();                              // single barrier per tile (double buffered)
    if (t + 1 < nT) {                             // prefetch next tile (overlaps mma)
      int k0 = (t + 1)*GBK;
      #pragma unroll
      for (int i = 0; i < 4; i++) {
        int f4 = i*256 + tid; int r = f4 >> 3; int c = (f4 & 7) << 2;
        ra[i] = *(const float4*)(A + (size_t)(bm0 + r)*K + k0 + c);
        rw[i] = *(const float4*)(W + (size_t)(bn0 + r)*K + k0 + c);
      }
    }
    uint32_t asb = smem_u32(as), wsb = smem_u32(ws);
    #pragma unroll
    for (int kk = 0; kk < 4; kk++) {
      unsigned af[2][4];
      #pragma unroll
      for (int mt = 0; mt < 2; mt++)
        ldsm4(af[mt][0], af[mt][1], af[mt][2], af[mt][3],
              asb + ((unsigned)((aRow + mt*16)*GPAD + aCol + kk*8) << 2));
      unsigned bf[8][2];
      #pragma unroll
      for (int np = 0; np < 4; np++) {
        unsigned r0, r1, r2, r3;
        ldsm4(r0, r1, r2, r3, wsb + ((unsigned)((bRow + np*16)*GPAD + bCol + kk*8) << 2));
        bf[2*np][0]=r0; bf[2*np][1]=r1; bf[2*np+1][0]=r2; bf[2*np+1][1]=r3;
      }
      #pragma unroll
      for (int mt = 0; mt < 2; mt++)
        #pragma unroll
        for (int nt = 0; nt < 8; nt++)
          mma_tf32(acc[mt][nt][0], acc[mt][nt][1], acc[mt][nt][2], acc[mt][nt][3],
                   af[mt][0], af[mt][1], af[mt][2], af[mt][3], bf[nt][0], bf[nt][1]);
    }
  }

  #pragma unroll
  for (int mt = 0; mt < 2; mt++)
    #pragma unroll
    for (int nt = 0; nt < 8; nt++) {
      int r = bm0 + wr*32 + mt*16 + (lane >> 2);
      int c = bn0 + wc*64 + nt*8 + (lane & 3)*2;
      float2 bb = *(const float2*)(bias + c);
      float2 v0 = make_float2(acc[mt][nt][0] + bb.x, acc[mt][nt][1] + bb.y);
      float2 v1 = make_float2(acc[mt][nt][2] + bb.x, acc[mt][nt][3] + bb.y);
      *(float2*)(C + (size_t)r*N + c)       = v0;
      *(float2*)(C + (size_t)(r + 8)*N + c) = v1;
    }
}

// ================= Fused attention: scores + softmax + attn write + PV =================
#define QB    32
#define SPAD  1028     // stride%32==4 -> conflict-free ldsm on P; %4==0 -> aligned
#define KPAD  68
#define QS_OFF  (QB*SPAD)                 // 32896 floats
#define KV_OFF  (QS_OFF + QB*KPAD)        // 35072 floats
#define ATT_SMEM_BYTES ((KV_OFF + 128*KPAD)*4)   // 175104 B

__global__ __launch_bounds__(256)
void attn_kernel(const float* __restrict__ Qp, const float* __restrict__ Kp,
                 const float* __restrict__ Vp,
                 float* __restrict__ attn_out, float* __restrict__ ctx)
{
  extern __shared__ float sm[];
  float* Ssc = sm;              // [32][1028] scores -> softmax -> P (tf32 bits)
  float* Qs  = sm + QS_OFF;     // [32][68]  tf32
  float* KVs = sm + KV_OFF;     // [128][68] tf32 (K chunk, then V chunk)
  const int tid = threadIdx.x, lane = tid & 31, wid = tid >> 5;
  const int qb = blockIdx.x, h = blockIdx.y, b = blockIdx.z;
  const int qg = lane >> 3, lr = lane & 7;
  const int mt  = wid & 1;                  // row-tile (16 rows)
  const int ng4 = (wid >> 1)*4;             // score ntile base (4 ntiles of 8 cols)
  const int aRowQ = mt*16 + (qg & 1)*8 + lr;
  const int aCol  = (qg >> 1)*4;
  const int bRowS = ng4*8 + (qg >> 1)*8 + lr;   // + np*16
  const int bColS = (qg & 1)*4;

  // ---- load Q tile 32x64 (tf32) ----
  #pragma unroll
  for (int i = 0; i < 2; i++) {
    int f4 = i*256 + tid; int r = f4 >> 4; int c = (f4 & 15) << 2;
    float4 v = *(const float4*)(Qp + (size_t)(b*SEQ + qb*QB + r)*D_MODEL + h*DKH + c);
    uint4 u; u.x=f2tf32(v.x); u.y=f2tf32(v.y); u.z=f2tf32(v.z); u.w=f2tf32(v.w);
    *(uint4*)(Qs + r*KPAD + c) = u;
  }

  // ---- phase 1: scores = (Q @ K^T) / 8 into Ssc ----
  uint32_t qsb = smem_u32(Qs), kvb = smem_u32(KVs), ssb = smem_u32(Ssc);
  for (int ch = 0; ch < 8; ch++) {
    if (ch > 0) __syncthreads();            // prior chunk consumed
    #pragma unroll
    for (int i = 0; i < 8; i++) {           // K chunk 128x64
      int f4 = i*256 + tid; int r = f4 >> 4; int c = (f4 & 15) << 2;
      float4 v = *(const float4*)(Kp + (size_t)(b*SEQ + ch*128 + r)*D_MODEL + h*DKH + c);
      uint4 u; u.x=f2tf32(v.x); u.y=f2tf32(v.y); u.z=f2tf32(v.z); u.w=f2tf32(v.w);
      *(uint4*)(KVs + r*KPAD + c) = u;
    }
    __syncthreads();                        // also covers Qs on first iter

    float sacc[4][4];
    #pragma unroll
    for (int j = 0; j < 4; j++) { sacc[j][0]=0.f; sacc[j][1]=0.f; sacc[j][2]=0.f; sacc[j][3]=0.f; }
    #pragma unroll
    for (int kk = 0; kk < 8; kk++) {
      unsigned a0,a1,a2,a3;
      ldsm4(a0,a1,a2,a3, qsb + ((unsigned)(aRowQ*KPAD + aCol + kk*8) << 2));
      unsigned bf[4][2];
      #pragma unroll
      for (int np = 0; np < 2; np++) {
        unsigned r0,r1,r2,r3;
        ldsm4(r0,r1,r2,r3, kvb + ((unsigned)((bRowS + np*16)*KPAD + bColS + kk*8) << 2));
        bf[2*np][0]=r0; bf[2*np][1]=r1; bf[2*np+1][0]=r2; bf[2*np+1][1]=r3;
      }
      #pragma unroll
      for (int j = 0; j < 4; j++)
        mma_tf32(sacc[j][0], sacc[j][1], sacc[j][2], sacc[j][3], a0,a1,a2,a3, bf[j][0], bf[j][1]);
    }
    const int srow = mt*16 + (lane >> 2);
    #pragma unroll
    for (int j = 0; j < 4; j++) {
      int scol = ch*128 + (ng4 + j)*8 + (lane & 3)*2;
      *(float2*)(Ssc + srow*SPAD + scol)     = make_float2(sacc[j][0]*0.125f, sacc[j][1]*0.125f);
      *(float2*)(Ssc + (srow+8)*SPAD + scol) = make_float2(sacc[j][2]*0.125f, sacc[j][3]*0.125f);
    }
  }
  __syncthreads();

  // ---- phase 2: softmax rows (4 rows per warp), write attention, leave tf32(P) in smem ----
  #pragma unroll
  for (int rr = 0; rr < 4; rr++) {
    int row = wid*4 + rr;
    float* srow = Ssc + row*SPAD;
    float mx = -1e30f;
    for (int i = lane; i < SEQ; i += 32) mx = fmaxf(mx, srow[i]);
    #pragma unroll
    for (int off = 16; off > 0; off >>= 1) mx = fmaxf(mx, __shfl_xor_sync(0xffffffffu, mx, off));
    float sum = 0.f;
    for (int i = lane; i < SEQ; i += 32) { float e = fast_exp(srow[i] - mx); srow[i] = e; sum += e; }
    #pragma unroll
    for (int off = 16; off > 0; off >>= 1) sum += __shfl_xor_sync(0xffffffffu, sum, off);
    float inv = 1.f / sum;
    float* arow = attn_out + (size_t)((b*NHEAD + h)*SEQ + qb*QB + row)*SEQ;
    for (int i = lane; i < SEQ; i += 32) {
      float p = srow[i] * inv;
      arow[i] = p;                                   // HBM: the only attention write
      srow[i] = __uint_as_float(f2tf32(p));          // keep tf32 bits for PV mma
    }
  }
  __syncthreads();

  // ---- phase 3: out = P @ V (accumulate across chunks) ----
  float oacc[2][4];
  #pragma unroll
  for (int j = 0; j < 2; j++) { oacc[j][0]=0.f; oacc[j][1]=0.f; oacc[j][2]=0.f; oacc[j][3]=0.f; }
  const int ntb = (wid >> 1)*2;             // 2 out-ntiles per warp
  for (int ch = 0; ch < 8; ch++) {
    if (ch > 0) __syncthreads();
    #pragma unroll
    for (int i = 0; i < 8; i++) {           // V chunk 128x64 (same layout as K)
      int f4 = i*256 + tid; int r = f4 >> 4; int c = (f4 & 15) << 2;
      float4 v = *(const float4*)(Vp + (size_t)(b*SEQ + ch*128 + r)*D_MODEL + h*DKH + c);
      uint4 u; u.x=f2tf32(v.x); u.y=f2tf32(v.y); u.z=f2tf32(v.z); u.w=f2tf32(v.w);
      *(uint4*)(KVs + r*KPAD + c) = u;
    }
    __syncthreads();
    #pragma unroll
    for (int kk = 0; kk < 16; kk++) {
      unsigned a0,a1,a2,a3;
      ldsm4(a0,a1,a2,a3, ssb + ((unsigned)(aRowQ*SPAD + ch*128 + aCol + kk*8) << 2));
      #pragma unroll
      for (int j = 0; j < 2; j++) {
        int nc = (ntb + j)*8 + (lane >> 2);
        unsigned b0 = __float_as_uint(KVs[(kk*8 +     (lane & 3))*KPAD + nc]);
        unsigned b1 = __float_as_uint(KVs[(kk*8 + 4 + (lane & 3))*KPAD + nc]);
        mma_tf32(oacc[j][0], oacc[j][1], oacc[j][2], oacc[j][3], a0,a1,a2,a3, b0, b1);
      }
    }
  }
  const int orow = b*SEQ + qb*QB + mt*16 + (lane >> 2);
  #pragma unroll
  for (int j = 0; j < 2; j++) {
    int ocol = h*DKH + (ntb + j)*8 + (lane & 3)*2;
    *(float2*)(ctx + (size_t)orow*D_MODEL + ocol)       = make_float2(oacc[j][0], oacc[j][1]);
    *(float2*)(ctx + (size_t)(orow + 8)*D_MODEL + ocol) = make_float2(oacc[j][2], oacc[j][3]);
  }
}

// ================= launch =================
extern "C" void kernel_launch(void* const* d_in, const int* in_sizes, int n_in,
                              void* d_out, int out_size)
{
  const float* q  = (const float*)d_in[0];
  const float* k  = (const float*)d_in[1];
  const float* v  = (const float*)d_in[2];
  const float* Wq = (const float*)d_in[3];
  const float* bq = (const float*)d_in[4];
  const float* Wk = (const float*)d_in[5];
  const float* bk = (const float*)d_in[6];
  const float* Wv = (const float*)d_in[7];
  const float* bv = (const float*)d_in[8];
  const float* Wo = (const float*)d_in[9];
  const float* bo = (const float*)d_in[10];

  float* out  = (float*)d_out;                 // (out, attention) concatenated
  float* attn = out + OUT_ELEMS;

  void *pq, *pk, *pv, *pctx;
  cudaGetSymbolAddress(&pq,   g_q);
  cudaGetSymbolAddress(&pk,   g_k);
  cudaGetSymbolAddress(&pv,   g_v);
  cudaGetSymbolAddress(&pctx, g_ctx);

  cudaFuncSetAttribute(gemm_tf32_kernel, cudaFuncAttributeMaxDynamicSharedMemorySize, GEMM_SMEM_BYTES);
  cudaFuncSetAttribute(attn_kernel,      cudaFuncAttributeMaxDynamicSharedMemorySize, ATT_SMEM_BYTES);

  dim3 gg(D_MODEL/GBN, MROWS/GBM);   // (8, 64)
  gemm_tf32_kernel<<<gg, 256, GEMM_SMEM_BYTES>>>(q, Wq, bq, (float*)pq,   MROWS, D_MODEL, D_MODEL);
  gemm_tf32_kernel<<<gg, 256, GEMM_SMEM_BYTES>>>(k, Wk, bk, (float*)pk,   MROWS, D_MODEL, D_MODEL);
  gemm_tf32_kernel<<<gg, 256, GEMM_SMEM_BYTES>>>(v, Wv, bv, (float*)pv,   MROWS, D_MODEL, D_MODEL);

  dim3 ga(SEQ/QB, NHEAD, BATCH);     // (32, 16, 8)
  attn_kernel<<<ga, 256, ATT_SMEM_BYTES>>>((const float*)pq, (const float*)pk, (const float*)pv,
                                           attn, (float*)pctx);

  gemm_tf32_kernel<<<gg, 256, GEMM_SMEM_BYTES>>>((const float*)pctx, Wo, bo, out, MROWS, D_MODEL, D_MODEL);
}

// round 5
// speedup vs baseline: 1.9762x; 1.9762x over previous
#include <cuda_runtime.h>
#include <cstdint>

#define D_MODEL 1024
#define NHEAD   16
#define DKH     64
#define BATCH   8
#define SEQ     1024
#define MROWS   (BATCH*SEQ)                   // 8192
#define OUT_ELEMS  (MROWS*D_MODEL)            // 8388608
#define ATTN_ELEMS (BATCH*NHEAD*SEQ*SEQ)      // 134217728

// ---------------- scratch (no cudaMalloc allowed) ----------------
__device__ float g_q  [MROWS*D_MODEL];
__device__ float g_k  [MROWS*D_MODEL];
__device__ float g_v  [MROWS*D_MODEL];
__device__ float g_ctx[MROWS*D_MODEL];

// ---------------- helpers ----------------
__device__ __forceinline__ unsigned f2tf32(float f){
  unsigned r; asm("cvt.rna.tf32.f32 %0, %1;" : "=r"(r) : "f"(f)); return r;
}
__device__ __forceinline__ uint32_t smem_u32(const void* p){
  return (uint32_t)__cvta_generic_to_shared(p);
}
__device__ __forceinline__ void ldsm4(unsigned &r0, unsigned &r1, unsigned &r2, unsigned &r3, uint32_t a){
  asm volatile("ldmatrix.sync.aligned.m8n8.x4.shared.b16 {%0,%1,%2,%3}, [%4];"
    : "=r"(r0),"=r"(r1),"=r"(r2),"=r"(r3) : "r"(a));
}
__device__ __forceinline__ void mma_tf32(float &d0,float &d1,float &d2,float &d3,
    unsigned a0,unsigned a1,unsigned a2,unsigned a3, unsigned b0,unsigned b1){
  asm volatile("mma.sync.aligned.m16n8k8.row.col.f32.tf32.tf32.f32 "
    "{%0,%1,%2,%3}, {%4,%5,%6,%7}, {%8,%9}, {%0,%1,%2,%3};"
    : "+f"(d0),"+f"(d1),"+f"(d2),"+f"(d3)
    : "r"(a0),"r"(a1),"r"(a2),"r"(a3),"r"(b0),"r"(b1));
}
// FFMA-only exp (avoids MUFU rt=8 for 134M exps). Valid for x <= 0 after max-sub.
__device__ __forceinline__ float fast_exp(float x){
  x = fmaxf(x, -80.f);
  float z  = fmaf(x, 1.4426950408889634f, 12582912.f);
  int   n  = __float_as_int(z) - 0x4B400000;
  float fn = z - 12582912.f;
  float t  = fmaf(x, 1.4426950408889634f, -fn);
  float u  = t * 0.6931471805599453f;
  float p  = fmaf(u, 0.0083333333f, 0.0416666667f);
  p = fmaf(u, p, 0.1666666667f);
  p = fmaf(u, p, 0.5f);
  p = fmaf(u, p, 1.0f);
  p = fmaf(u, p, 1.0f);
  return __int_as_float((n + 127) << 23) * p;
}

// ================= TF32 GEMM:  C[M,N] = A[M,K] @ W[N,K]^T + bias[N] =================
// (unchanged from the passing R2 kernel)
#define GBM 128
#define GBN 128
#define GBK 32
#define GPAD 36
#define GEMM_SMEM_BYTES (4*GBM*GPAD*4)

__global__ __launch_bounds__(256)
void gemm_tf32_kernel(const float* __restrict__ A, const float* __restrict__ W,
                      const float* __restrict__ bias, float* __restrict__ C,
                      int M, int N, int K)
{
  extern __shared__ float sm[];
  float* As = sm;
  float* Ws = sm + 2*GBM*GPAD;
  const int tid = threadIdx.x, lane = tid & 31, wid = tid >> 5;
  const int wr = wid & 3, wc = wid >> 2;
  const int bm0 = blockIdx.y * GBM, bn0 = blockIdx.x * GBN;
  const int qg = lane >> 3, lr = lane & 7;
  const int aRow = wr*32 + (qg & 1)*8 + lr;
  const int aCol = (qg >> 1)*4;
  const int bRow = wc*64 + (qg >> 1)*8 + lr;
  const int bCol = (qg & 1)*4;

  float acc[2][8][4];
  #pragma unroll
  for (int mt = 0; mt < 2; mt++)
    #pragma unroll
    for (int nt = 0; nt < 8; nt++)
      #pragma unroll
      for (int j = 0; j < 4; j++) acc[mt][nt][j] = 0.f;

  float4 ra[4], rw[4];
  const int nT = K / GBK;

  #pragma unroll
  for (int i = 0; i < 4; i++) {
    int f4 = i*256 + tid; int r = f4 >> 3; int c = (f4 & 7) << 2;
    ra[i] = *(const float4*)(A + (size_t)(bm0 + r)*K + c);
    rw[i] = *(const float4*)(W + (size_t)(bn0 + r)*K + c);
  }

  for (int t = 0; t < nT; t++) {
    float* as = As + (t & 1)*GBM*GPAD;
    float* ws = Ws + (t & 1)*GBM*GPAD;
    #pragma unroll
    for (int i = 0; i < 4; i++) {
      int f4 = i*256 + tid; int r = f4 >> 3; int c = (f4 & 7) << 2;
      uint4 ua; ua.x=f2tf32(ra[i].x); ua.y=f2tf32(ra[i].y); ua.z=f2tf32(ra[i].z); ua.w=f2tf32(ra[i].w);
      uint4 uw; uw.x=f2tf32(rw[i].x); uw.y=f2tf32(rw[i].y); uw.z=f2tf32(rw[i].z); uw.w=f2tf32(rw[i].w);
      *(uint4*)(as + r*GPAD + c) = ua;
      *(uint4*)(ws + r*GPAD + c) = uw;
    }
    __syncthreads();
    if (t + 1 < nT) {
      int k0 = (t + 1)*GBK;
      #pragma unroll
      for (int i = 0; i < 4; i++) {
        int f4 = i*256 + tid; int r = f4 >> 3; int c = (f4 & 7) << 2;
        ra[i] = *(const float4*)(A + (size_t)(bm0 + r)*K + k0 + c);
        rw[i] = *(const float4*)(W + (size_t)(bn0 + r)*K + k0 + c);
      }
    }
    uint32_t asb = smem_u32(as), wsb = smem_u32(ws);
    #pragma unroll
    for (int kk = 0; kk < 4; kk++) {
      unsigned af[2][4];
      #pragma unroll
      for (int mt = 0; mt < 2; mt++)
        ldsm4(af[mt][0], af[mt][1], af[mt][2], af[mt][3],
              asb + ((unsigned)((aRow + mt*16)*GPAD + aCol + kk*8) << 2));
      unsigned bf[8][2];
      #pragma unroll
      for (int np = 0; np < 4; np++) {
        unsigned r0, r1, r2, r3;
        ldsm4(r0, r1, r2, r3, wsb + ((unsigned)((bRow + np*16)*GPAD + bCol + kk*8) << 2));
        bf[2*np][0]=r0; bf[2*np][1]=r1; bf[2*np+1][0]=r2; bf[2*np+1][1]=r3;
      }
      #pragma unroll
      for (int mt = 0; mt < 2; mt++)
        #pragma unroll
        for (int nt = 0; nt < 8; nt++)
          mma_tf32(acc[mt][nt][0], acc[mt][nt][1], acc[mt][nt][2], acc[mt][nt][3],
                   af[mt][0], af[mt][1], af[mt][2], af[mt][3], bf[nt][0], bf[nt][1]);
    }
  }

  #pragma unroll
  for (int mt = 0; mt < 2; mt++)
    #pragma unroll
    for (int nt = 0; nt < 8; nt++) {
      int r = bm0 + wr*32 + mt*16 + (lane >> 2);
      int c = bn0 + wc*64 + nt*8 + (lane & 3)*2;
      float2 bb = *(const float2*)(bias + c);
      float2 v0 = make_float2(acc[mt][nt][0] + bb.x, acc[mt][nt][1] + bb.y);
      float2 v1 = make_float2(acc[mt][nt][2] + bb.x, acc[mt][nt][3] + bb.y);
      *(float2*)(C + (size_t)r*N + c)       = v0;
      *(float2*)(C + (size_t)(r + 8)*N + c) = v1;
    }
}

// ================= scores: S[b,h,q,k] = (Qh @ Kh^T) / 8  (raw, pre-softmax) =================
// 128x128 output tile per CTA, K=64, single-shot smem, same fragment layout as the GEMM.
#define SC_PAD 68
#define SC_SMEM (2*128*SC_PAD*4)     // 69632 B

__global__ __launch_bounds__(256)
void scores_kernel(const float* __restrict__ Qp, const float* __restrict__ Kp,
                   float* __restrict__ Sc)
{
  extern __shared__ float sm[];
  float* As = sm;                    // [128][68] q-rows, tf32
  float* Bs = sm + 128*SC_PAD;       // [128][68] k-rows, tf32
  const int tid = threadIdx.x, lane = tid & 31, wid = tid >> 5;
  const int wr = wid & 3, wc = wid >> 2;
  const int bh = blockIdx.z, b = bh >> 4, h = bh & 15;
  const int bm0 = blockIdx.y * 128, bn0 = blockIdx.x * 128;
  const int qg = lane >> 3, lr = lane & 7;
  const int aRow = wr*32 + (qg & 1)*8 + lr;
  const int aCol = (qg >> 1)*4;
  const int bRow = wc*64 + (qg >> 1)*8 + lr;
  const int bCol = (qg & 1)*4;

  // load Q tile 128x64 and K tile 128x64 (8 float4 each per thread)
  #pragma unroll
  for (int i = 0; i < 8; i++) {
    int f4 = i*256 + tid; int r = f4 >> 4; int c = (f4 & 15) << 2;
    float4 va = *(const float4*)(Qp + (size_t)(b*SEQ + bm0 + r)*D_MODEL + h*DKH + c);
    float4 vb = *(const float4*)(Kp + (size_t)(b*SEQ + bn0 + r)*D_MODEL + h*DKH + c);
    uint4 ua; ua.x=f2tf32(va.x); ua.y=f2tf32(va.y); ua.z=f2tf32(va.z); ua.w=f2tf32(va.w);
    uint4 ub; ub.x=f2tf32(vb.x); ub.y=f2tf32(vb.y); ub.z=f2tf32(vb.z); ub.w=f2tf32(vb.w);
    *(uint4*)(As + r*SC_PAD + c) = ua;
    *(uint4*)(Bs + r*SC_PAD + c) = ub;
  }
  __syncthreads();

  float acc[2][8][4];
  #pragma unroll
  for (int mt = 0; mt < 2; mt++)
    #pragma unroll
    for (int nt = 0; nt < 8; nt++)
      #pragma unroll
      for (int j = 0; j < 4; j++) acc[mt][nt][j] = 0.f;

  uint32_t asb = smem_u32(As), bsb = smem_u32(Bs);
  #pragma unroll
  for (int kk = 0; kk < 8; kk++) {
    unsigned af[2][4];
    #pragma unroll
    for (int mt = 0; mt < 2; mt++)
      ldsm4(af[mt][0], af[mt][1], af[mt][2], af[mt][3],
            asb + ((unsigned)((aRow + mt*16)*SC_PAD + aCol + kk*8) << 2));
    unsigned bf[8][2];
    #pragma unroll
    for (int np = 0; np < 4; np++) {
      unsigned r0, r1, r2, r3;
      ldsm4(r0, r1, r2, r3, bsb + ((unsigned)((bRow + np*16)*SC_PAD + bCol + kk*8) << 2));
      bf[2*np][0]=r0; bf[2*np][1]=r1; bf[2*np+1][0]=r2; bf[2*np+1][1]=r3;
    }
    #pragma unroll
    for (int mt = 0; mt < 2; mt++)
      #pragma unroll
      for (int nt = 0; nt < 8; nt++)
        mma_tf32(acc[mt][nt][0], acc[mt][nt][1], acc[mt][nt][2], acc[mt][nt][3],
                 af[mt][0], af[mt][1], af[mt][2], af[mt][3], bf[nt][0], bf[nt][1]);
  }

  #pragma unroll
  for (int mt = 0; mt < 2; mt++)
    #pragma unroll
    for (int nt = 0; nt < 8; nt++) {
      int r = bm0 + wr*32 + mt*16 + (lane >> 2);
      int c = bn0 + wc*64 + nt*8 + (lane & 3)*2;
      float* base = Sc + (size_t)bh*SEQ*SEQ;
      *(float2*)(base + (size_t)r*SEQ + c) =
          make_float2(acc[mt][nt][0]*0.125f, acc[mt][nt][1]*0.125f);
      *(float2*)(base + (size_t)(r + 8)*SEQ + c) =
          make_float2(acc[mt][nt][2]*0.125f, acc[mt][nt][3]*0.125f);
    }
}

// ================= softmax: normalize each length-1024 row in place =================
// one warp per row, 32 floats per lane in registers; pure streaming.
__global__ __launch_bounds__(256)
void softmax_kernel(float* __restrict__ attn)
{
  const int lane = threadIdx.x & 31, w = threadIdx.x >> 5;
  const size_t row = (size_t)blockIdx.x * 8 + w;
  float4* rp = (float4*)(attn + row * SEQ);
  float4 r[8];
  #pragma unroll
  for (int i = 0; i < 8; i++) r[i] = rp[lane + i*32];

  float mx = -1e30f;
  #pragma unroll
  for (int i = 0; i < 8; i++) {
    mx = fmaxf(mx, fmaxf(fmaxf(r[i].x, r[i].y), fmaxf(r[i].z, r[i].w)));
  }
  #pragma unroll
  for (int off = 16; off > 0; off >>= 1) mx = fmaxf(mx, __shfl_xor_sync(0xffffffffu, mx, off));

  float sum = 0.f;
  #pragma unroll
  for (int i = 0; i < 8; i++) {
    r[i].x = fast_exp(r[i].x - mx);
    r[i].y = fast_exp(r[i].y - mx);
    r[i].z = fast_exp(r[i].z - mx);
    r[i].w = fast_exp(r[i].w - mx);
    sum += (r[i].x + r[i].y) + (r[i].z + r[i].w);
  }
  #pragma unroll
  for (int off = 16; off > 0; off >>= 1) sum += __shfl_xor_sync(0xffffffffu, sum, off);
  float inv = 1.f / sum;

  #pragma unroll
  for (int i = 0; i < 8; i++) {
    r[i].x *= inv; r[i].y *= inv; r[i].z *= inv; r[i].w *= inv;
    rp[lane + i*32] = r[i];
  }
}

// ================= PV: ctx[b,q,h*64+n] = sum_k P[b,h,q,k] * V[b,k,h*64+n] =================
// CTA = (mtile of 128 q-rows, bh). Stream P in 128-col chunks; V chunk as [k][n] smem.
#define PV_PPAD 132
#define PV_VPAD 68
#define PV_SMEM ((128*PV_PPAD + 128*PV_VPAD)*4)   // 102400 B

__global__ __launch_bounds__(256)
void pv_kernel(const float* __restrict__ attn, const float* __restrict__ Vp,
               float* __restrict__ ctx)
{
  extern __shared__ float sm[];
  float* Ps = sm;                     // [128][132] tf32(P chunk)
  float* Vs = sm + 128*PV_PPAD;       // [128][68]  tf32(V chunk), rows = k
  const int tid = threadIdx.x, lane = tid & 31, wid = tid >> 5;
  const int bh = blockIdx.y, b = bh >> 4, h = bh & 15;
  const int bm0 = blockIdx.x * 128;
  const int qg = lane >> 3, lr = lane & 7;
  const int aRow = wid*16 + (qg & 1)*8 + lr;     // warp owns 16 q-rows
  const int aCol = (qg >> 1)*4;

  const float* Pbase = attn + (size_t)bh*SEQ*SEQ + (size_t)bm0*SEQ;

  float acc[8][4];
  #pragma unroll
  for (int nt = 0; nt < 8; nt++)
    #pragma unroll
    for (int j = 0; j < 4; j++) acc[nt][j] = 0.f;

  uint32_t psb = smem_u32(Ps);
  for (int ch = 0; ch < 8; ch++) {
    if (ch > 0) __syncthreads();
    // P chunk 128x128 -> tf32 smem
    #pragma unroll
    for (int i = 0; i < 16; i++) {
      int f4 = i*256 + tid; int r = f4 >> 5; int c = (f4 & 31) << 2;
      float4 v = *(const float4*)(Pbase + (size_t)r*SEQ + ch*128 + c);
      uint4 u; u.x=f2tf32(v.x); u.y=f2tf32(v.y); u.z=f2tf32(v.z); u.w=f2tf32(v.w);
      *(uint4*)(Ps + r*PV_PPAD + c) = u;
    }
    // V chunk 128x64 -> tf32 smem [k][n]
    #pragma unroll
    for (int i = 0; i < 8; i++) {
      int f4 = i*256 + tid; int r = f4 >> 4; int c = (f4 & 15) << 2;
      float4 v = *(const float4*)(Vp + (size_t)(b*SEQ + ch*128 + r)*D_MODEL + h*DKH + c);
      uint4 u; u.x=f2tf32(v.x); u.y=f2tf32(v.y); u.z=f2tf32(v.z); u.w=f2tf32(v.w);
      *(uint4*)(Vs + r*PV_VPAD + c) = u;
    }
    __syncthreads();
    #pragma unroll
    for (int kk = 0; kk < 16; kk++) {
      unsigned a0,a1,a2,a3;
      ldsm4(a0,a1,a2,a3, psb + ((unsigned)(aRow*PV_PPAD + aCol + kk*8) << 2));
      #pragma unroll
      for (int nt = 0; nt < 8; nt++) {
        int nc = nt*8 + (lane >> 2);
        unsigned b0 = __float_as_uint(Vs[(kk*8 +     (lane & 3))*PV_VPAD + nc]);
        unsigned b1 = __float_as_uint(Vs[(kk*8 + 4 + (lane & 3))*PV_VPAD + nc]);
        mma_tf32(acc[nt][0], acc[nt][1], acc[nt][2], acc[nt][3], a0,a1,a2,a3, b0, b1);
      }
    }
  }

  const int q = bm0 + wid*16 + (lane >> 2);
  #pragma unroll
  for (int nt = 0; nt < 8; nt++) {
    int c = h*DKH + nt*8 + (lane & 3)*2;
    *(float2*)(ctx + (size_t)(b*SEQ + q)*D_MODEL + c)     = make_float2(acc[nt][0], acc[nt][1]);
    *(float2*)(ctx + (size_t)(b*SEQ + q + 8)*D_MODEL + c) = make_float2(acc[nt][2], acc[nt][3]);
  }
}

// ================= launch =================
extern "C" void kernel_launch(void* const* d_in, const int* in_sizes, int n_in,
                              void* d_out, int out_size)
{
  const float* q  = (const float*)d_in[0];
  const float* k  = (const float*)d_in[1];
  const float* v  = (const float*)d_in[2];
  const float* Wq = (const float*)d_in[3];
  const float* bq = (const float*)d_in[4];
  const float* Wk = (const float*)d_in[5];
  const float* bk = (const float*)d_in[6];
  const float* Wv = (const float*)d_in[7];
  const float* bv = (const float*)d_in[8];
  const float* Wo = (const float*)d_in[9];
  const float* bo = (const float*)d_in[10];

  float* out  = (float*)d_out;                 // (out, attention) concatenated
  float* attn = out + OUT_ELEMS;

  void *pq, *pk, *pv, *pctx;
  cudaGetSymbolAddress(&pq,   g_q);
  cudaGetSymbolAddress(&pk,   g_k);
  cudaGetSymbolAddress(&pv,   g_v);
  cudaGetSymbolAddress(&pctx, g_ctx);

  cudaFuncSetAttribute(gemm_tf32_kernel, cudaFuncAttributeMaxDynamicSharedMemorySize, GEMM_SMEM_BYTES);
  cudaFuncSetAttribute(scores_kernel,    cudaFuncAttributeMaxDynamicSharedMemorySize, SC_SMEM);
  cudaFuncSetAttribute(pv_kernel,        cudaFuncAttributeMaxDynamicSharedMemorySize, PV_SMEM);

  dim3 gg(D_MODEL/GBN, MROWS/GBM);   // (8, 64)
  gemm_tf32_kernel<<<gg, 256, GEMM_SMEM_BYTES>>>(q, Wq, bq, (float*)pq, MROWS, D_MODEL, D_MODEL);
  gemm_tf32_kernel<<<gg, 256, GEMM_SMEM_BYTES>>>(k, Wk, bk, (float*)pk, MROWS, D_MODEL, D_MODEL);
  gemm_tf32_kernel<<<gg, 256, GEMM_SMEM_BYTES>>>(v, Wv, bv, (float*)pv, MROWS, D_MODEL, D_MODEL);

  dim3 gs(SEQ/128, SEQ/128, BATCH*NHEAD);      // (8, 8, 128)
  scores_kernel<<<gs, 256, SC_SMEM>>>((const float*)pq, (const float*)pk, attn);

  softmax_kernel<<<(BATCH*NHEAD*SEQ)/8, 256>>>(attn);

  dim3 gp(SEQ/128, BATCH*NHEAD);               // (8, 128)
  pv_kernel<<<gp, 256, PV_SMEM>>>(attn, (const float*)pv, (float*)pctx);

  gemm_tf32_kernel<<<gg, 256, GEMM_SMEM_BYTES>>>((const float*)pctx, Wo, bo, out, MROWS, D_MODEL, D_MODEL);
}

// round 6
// speedup vs baseline: 2.0486x; 1.0366x over previous
#include <cuda_runtime.h>
#include <cstdint>

#define D_MODEL 1024
#define NHEAD   16
#define DKH     64
#define BATCH   8
#define SEQ     1024
#define MROWS   (BATCH*SEQ)                   // 8192
#define OUT_ELEMS  (MROWS*D_MODEL)            // 8388608
#define ATTN_ELEMS (BATCH*NHEAD*SEQ*SEQ)      // 134217728
#define NROWS_TOT  (BATCH*NHEAD*SEQ)          // 131072 attention rows

// ---------------- scratch (no cudaMalloc allowed) ----------------
__device__ float g_q  [MROWS*D_MODEL];
__device__ float g_k  [MROWS*D_MODEL];
__device__ float g_v  [MROWS*D_MODEL];
__device__ float g_ctx[MROWS*D_MODEL];
__device__ float g_statm[NROWS_TOT*8];        // per (row, bn-tile) max
__device__ float g_stats[NROWS_TOT*8];        // per (row, bn-tile) sum-exp
__device__ float2 g_rowstat[NROWS_TOT];       // per row (M, 1/S)

// ---------------- helpers ----------------
__device__ __forceinline__ unsigned f2tf32(float f){
  unsigned r; asm("cvt.rna.tf32.f32 %0, %1;" : "=r"(r) : "f"(f)); return r;
}
__device__ __forceinline__ uint32_t smem_u32(const void* p){
  return (uint32_t)__cvta_generic_to_shared(p);
}
__device__ __forceinline__ void ldsm4(unsigned &r0, unsigned &r1, unsigned &r2, unsigned &r3, uint32_t a){
  asm volatile("ldmatrix.sync.aligned.m8n8.x4.shared.b16 {%0,%1,%2,%3}, [%4];"
    : "=r"(r0),"=r"(r1),"=r"(r2),"=r"(r3) : "r"(a));
}
__device__ __forceinline__ void mma_tf32(float &d0,float &d1,float &d2,float &d3,
    unsigned a0,unsigned a1,unsigned a2,unsigned a3, unsigned b0,unsigned b1){
  asm volatile("mma.sync.aligned.m16n8k8.row.col.f32.tf32.tf32.f32 "
    "{%0,%1,%2,%3}, {%4,%5,%6,%7}, {%8,%9}, {%0,%1,%2,%3};"
    : "+f"(d0),"+f"(d1),"+f"(d2),"+f"(d3)
    : "r"(a0),"r"(a1),"r"(a2),"r"(a3),"r"(b0),"r"(b1));
}
// FFMA-only exp (avoids MUFU rt=8 for 134M exps). Valid for x <= 0 after max-sub.
__device__ __forceinline__ float fast_exp(float x){
  x = fmaxf(x, -80.f);
  float z  = fmaf(x, 1.4426950408889634f, 12582912.f);
  int   n  = __float_as_int(z) - 0x4B400000;
  float fn = z - 12582912.f;
  float t  = fmaf(x, 1.4426950408889634f, -fn);
  float u  = t * 0.6931471805599453f;
  float p  = fmaf(u, 0.0083333333f, 0.0416666667f);
  p = fmaf(u, p, 0.1666666667f);
  p = fmaf(u, p, 0.5f);
  p = fmaf(u, p, 1.0f);
  p = fmaf(u, p, 1.0f);
  return __int_as_float((n + 127) << 23) * p;
}

// ================= TF32 GEMM body:  C[8192,1024] = A @ W^T + bias =================
#define GBM 128
#define GBN 128
#define GBK 32
#define GPAD 36
#define GEMM_SMEM_BYTES (4*GBM*GPAD*4)
#define GK 1024
#define GN 1024

__device__ __forceinline__ void gemm_body(const float* __restrict__ A,
                                          const float* __restrict__ W,
                                          const float* __restrict__ bias,
                                          float* __restrict__ C, float* sm)
{
  float* As = sm;
  float* Ws = sm + 2*GBM*GPAD;
  const int tid = threadIdx.x, lane = tid & 31, wid = tid >> 5;
  const int wr = wid & 3, wc = wid >> 2;
  const int bm0 = blockIdx.y * GBM, bn0 = blockIdx.x * GBN;
  const int qg = lane >> 3, lr = lane & 7;
  const int aRow = wr*32 + (qg & 1)*8 + lr;
  const int aCol = (qg >> 1)*4;
  const int bRow = wc*64 + (qg >> 1)*8 + lr;
  const int bCol = (qg & 1)*4;

  float acc[2][8][4];
  #pragma unroll
  for (int mt = 0; mt < 2; mt++)
    #pragma unroll
    for (int nt = 0; nt < 8; nt++)
      #pragma unroll
      for (int j = 0; j < 4; j++) acc[mt][nt][j] = 0.f;

  float4 ra[4], rw[4];
  const int nT = GK / GBK;

  #pragma unroll
  for (int i = 0; i < 4; i++) {
    int f4 = i*256 + tid; int r = f4 >> 3; int c = (f4 & 7) << 2;
    ra[i] = *(const float4*)(A + (size_t)(bm0 + r)*GK + c);
    rw[i] = *(const float4*)(W + (size_t)(bn0 + r)*GK + c);
  }

  for (int t = 0; t < nT; t++) {
    float* as = As + (t & 1)*GBM*GPAD;
    float* ws = Ws + (t & 1)*GBM*GPAD;
    #pragma unroll
    for (int i = 0; i < 4; i++) {
      int f4 = i*256 + tid; int r = f4 >> 3; int c = (f4 & 7) << 2;
      uint4 ua; ua.x=f2tf32(ra[i].x); ua.y=f2tf32(ra[i].y); ua.z=f2tf32(ra[i].z); ua.w=f2tf32(ra[i].w);
      uint4 uw; uw.x=f2tf32(rw[i].x); uw.y=f2tf32(rw[i].y); uw.z=f2tf32(rw[i].z); uw.w=f2tf32(rw[i].w);
      *(uint4*)(as + r*GPAD + c) = ua;
      *(uint4*)(ws + r*GPAD + c) = uw;
    }
    __syncthreads();
    if (t + 1 < nT) {
      int k0 = (t + 1)*GBK;
      #pragma unroll
      for (int i = 0; i < 4; i++) {
        int f4 = i*256 + tid; int r = f4 >> 3; int c = (f4 & 7) << 2;
        ra[i] = *(const float4*)(A + (size_t)(bm0 + r)*GK + k0 + c);
        rw[i] = *(const float4*)(W + (size_t)(bn0 + r)*GK + k0 + c);
      }
    }
    uint32_t asb = smem_u32(as), wsb = smem_u32(ws);
    #pragma unroll
    for (int kk = 0; kk < 4; kk++) {
      unsigned af[2][4];
      #pragma unroll
      for (int mt = 0; mt < 2; mt++)
        ldsm4(af[mt][0], af[mt][1], af[mt][2], af[mt][3],
              asb + ((unsigned)((aRow + mt*16)*GPAD + aCol + kk*8) << 2));
      unsigned bf[8][2];
      #pragma unroll
      for (int np = 0; np < 4; np++) {
        unsigned r0, r1, r2, r3;
        ldsm4(r0, r1, r2, r3, wsb + ((unsigned)((bRow + np*16)*GPAD + bCol + kk*8) << 2));
        bf[2*np][0]=r0; bf[2*np][1]=r1; bf[2*np+1][0]=r2; bf[2*np+1][1]=r3;
      }
      #pragma unroll
      for (int mt = 0; mt < 2; mt++)
        #pragma unroll
        for (int nt = 0; nt < 8; nt++)
          mma_tf32(acc[mt][nt][0], acc[mt][nt][1], acc[mt][nt][2], acc[mt][nt][3],
                   af[mt][0], af[mt][1], af[mt][2], af[mt][3], bf[nt][0], bf[nt][1]);
    }
  }

  #pragma unroll
  for (int mt = 0; mt < 2; mt++)
    #pragma unroll
    for (int nt = 0; nt < 8; nt++) {
      int r = bm0 + wr*32 + mt*16 + (lane >> 2);
      int c = bn0 + wc*64 + nt*8 + (lane & 3)*2;
      float2 bb = *(const float2*)(bias + c);
      float2 v0 = make_float2(acc[mt][nt][0] + bb.x, acc[mt][nt][1] + bb.y);
      float2 v1 = make_float2(acc[mt][nt][2] + bb.x, acc[mt][nt][3] + bb.y);
      *(float2*)(C + (size_t)r*GN + c)       = v0;
      *(float2*)(C + (size_t)(r + 8)*GN + c) = v1;
    }
}

__global__ __launch_bounds__(256)
void gemm_tf32_kernel(const float* __restrict__ A, const float* __restrict__ W,
                      const float* __restrict__ bias, float* __restrict__ C)
{
  extern __shared__ float sm[];
  gemm_body(A, W, bias, C, sm);
}

// QKV fused: blockIdx.z selects which projection.
__global__ __launch_bounds__(256)
void qkv_gemm_kernel(const float* __restrict__ q, const float* __restrict__ k,
                     const float* __restrict__ v,
                     const float* __restrict__ Wq, const float* __restrict__ Wk,
                     const float* __restrict__ Wv,
                     const float* __restrict__ bq, const float* __restrict__ bk,
                     const float* __restrict__ bv,
                     float* __restrict__ Cq, float* __restrict__ Ck, float* __restrict__ Cv)
{
  extern __shared__ float sm[];
  const float *A, *W, *bias; float* C;
  if (blockIdx.z == 0)      { A = q; W = Wq; bias = bq; C = Cq; }
  else if (blockIdx.z == 1) { A = k; W = Wk; bias = bk; C = Ck; }
  else                      { A = v; W = Wv; bias = bv; C = Cv; }
  gemm_body(A, W, bias, C, sm);
}

// ======== scores: S[b,h,q,k] = (Q/8 @ K^T) raw + per-tile row stats (m, sumexp) ========
#define SC_PAD 68
#define SC_SMEM (2*128*SC_PAD*4)     // 69632 B

__global__ __launch_bounds__(256)
void scores_kernel(const float* __restrict__ Qp, const float* __restrict__ Kp,
                   float* __restrict__ Sc)
{
  extern __shared__ float sm[];
  float* As = sm;                    // [128][68] q-rows (pre-scaled 1/8), tf32
  float* Bs = sm + 128*SC_PAD;       // [128][68] k-rows, tf32
  const int tid = threadIdx.x, lane = tid & 31, wid = tid >> 5;
  const int wr = wid & 3, wc = wid >> 2;
  const int bh = blockIdx.z, b = bh >> 4, h = bh & 15;
  const int bm0 = blockIdx.y * 128, bn0 = blockIdx.x * 128;
  const int qg = lane >> 3, lr = lane & 7;
  const int aRow = wr*32 + (qg & 1)*8 + lr;
  const int aCol = (qg >> 1)*4;
  const int bRow = wc*64 + (qg >> 1)*8 + lr;
  const int bCol = (qg & 1)*4;

  #pragma unroll
  for (int i = 0; i < 8; i++) {
    int f4 = i*256 + tid; int r = f4 >> 4; int c = (f4 & 15) << 2;
    float4 va = *(const float4*)(Qp + (size_t)(b*SEQ + bm0 + r)*D_MODEL + h*DKH + c);
    float4 vb = *(const float4*)(Kp + (size_t)(b*SEQ + bn0 + r)*D_MODEL + h*DKH + c);
    uint4 ua; ua.x=f2tf32(0.125f*va.x); ua.y=f2tf32(0.125f*va.y);
              ua.z=f2tf32(0.125f*va.z); ua.w=f2tf32(0.125f*va.w);
    uint4 ub; ub.x=f2tf32(vb.x); ub.y=f2tf32(vb.y); ub.z=f2tf32(vb.z); ub.w=f2tf32(vb.w);
    *(uint4*)(As + r*SC_PAD + c) = ua;
    *(uint4*)(Bs + r*SC_PAD + c) = ub;
  }
  __syncthreads();

  float acc[2][8][4];
  #pragma unroll
  for (int mt = 0; mt < 2; mt++)
    #pragma unroll
    for (int nt = 0; nt < 8; nt++)
      #pragma unroll
      for (int j = 0; j < 4; j++) acc[mt][nt][j] = 0.f;

  uint32_t asb = smem_u32(As), bsb = smem_u32(Bs);
  #pragma unroll
  for (int kk = 0; kk < 8; kk++) {
    unsigned af[2][4];
    #pragma unroll
    for (int mt = 0; mt < 2; mt++)
      ldsm4(af[mt][0], af[mt][1], af[mt][2], af[mt][3],
            asb + ((unsigned)((aRow + mt*16)*SC_PAD + aCol + kk*8) << 2));
    unsigned bf[8][2];
    #pragma unroll
    for (int np = 0; np < 4; np++) {
      unsigned r0, r1, r2, r3;
      ldsm4(r0, r1, r2, r3, bsb + ((unsigned)((bRow + np*16)*SC_PAD + bCol + kk*8) << 2));
      bf[2*np][0]=r0; bf[2*np][1]=r1; bf[2*np+1][0]=r2; bf[2*np+1][1]=r3;
    }
    #pragma unroll
    for (int mt = 0; mt < 2; mt++)
      #pragma unroll
      for (int nt = 0; nt < 8; nt++)
        mma_tf32(acc[mt][nt][0], acc[mt][nt][1], acc[mt][nt][2], acc[mt][nt][3],
                 af[mt][0], af[mt][1], af[mt][2], af[mt][3], bf[nt][0], bf[nt][1]);
  }

  // write raw scores
  float* base = Sc + (size_t)bh*SEQ*SEQ;
  #pragma unroll
  for (int mt = 0; mt < 2; mt++)
    #pragma unroll
    for (int nt = 0; nt < 8; nt++) {
      int r = bm0 + wr*32 + mt*16 + (lane >> 2);
      int c = bn0 + wc*64 + nt*8 + (lane & 3)*2;
      *(float2*)(base + (size_t)r*SEQ + c)       = make_float2(acc[mt][nt][0], acc[mt][nt][1]);
      *(float2*)(base + (size_t)(r + 8)*SEQ + c) = make_float2(acc[mt][nt][2], acc[mt][nt][3]);
    }

  // ---- per-tile row stats: m = max over 128 cols, sigma = sum exp(s - m) ----
  __syncthreads();                   // done with As/Bs smem -> reuse
  float* mp = sm;                    // [2][128] per-wc row max
  float* sp = sm + 256;              // [2][128] per-wc row sumexp
  // local max per (mt, h)
  float mloc[2][2];
  #pragma unroll
  for (int mt = 0; mt < 2; mt++)
    #pragma unroll
    for (int hh = 0; hh < 2; hh++) {
      float m = -1e30f;
      #pragma unroll
      for (int nt = 0; nt < 8; nt++)
        m = fmaxf(m, fmaxf(acc[mt][nt][2*hh], acc[mt][nt][2*hh+1]));
      #pragma unroll
      for (int off = 1; off <= 2; off <<= 1)
        m = fmaxf(m, __shfl_xor_sync(0xffffffffu, m, off));
      mloc[mt][hh] = m;
      if ((lane & 3) == 0)
        mp[wc*128 + wr*32 + mt*16 + hh*8 + (lane >> 2)] = m;
    }
  __syncthreads();
  // final max + sumexp
  #pragma unroll
  for (int mt = 0; mt < 2; mt++)
    #pragma unroll
    for (int hh = 0; hh < 2; hh++) {
      int rl = wr*32 + mt*16 + hh*8 + (lane >> 2);
      float m = fmaxf(mp[rl], mp[128 + rl]);
      float s = 0.f;
      #pragma unroll
      for (int nt = 0; nt < 8; nt++)
        s += fast_exp(acc[mt][nt][2*hh] - m) + fast_exp(acc[mt][nt][2*hh+1] - m);
      #pragma unroll
      for (int off = 1; off <= 2; off <<= 1)
        s += __shfl_xor_sync(0xffffffffu, s, off);
      if ((lane & 3) == 0) sp[wc*128 + rl] = s;
    }
  __syncthreads();
  if (tid < 128) {
    float m = fmaxf(mp[tid], mp[128 + tid]);
    float s = sp[tid] + sp[128 + tid];
    size_t idx = ((size_t)(bh*SEQ + bm0 + tid))*8 + blockIdx.x;
    g_statm[idx] = m;
    g_stats[idx] = s;
  }
}

// ======== combine: per row M = max_t m_t, S = sum_t exp(m_t - M) * sigma_t ========
__global__ __launch_bounds__(256)
void combine_kernel()
{
  int g = blockIdx.x*256 + threadIdx.x;     // 131072 rows
  const float* mrow = g_statm + (size_t)g*8;
  const float* srow = g_stats + (size_t)g*8;
  float M = -1e30f;
  #pragma unroll
  for (int t = 0; t < 8; t++) M = fmaxf(M, mrow[t]);
  float S = 0.f;
  #pragma unroll
  for (int t = 0; t < 8; t++) S += fast_exp(mrow[t] - M) * srow[t];
  g_rowstat[g] = make_float2(M, 1.f / S);
}

// ======== pv: normalize raw scores inline, write attn in place, ctx = P @ V ========
#define PV_PPAD 132
#define PV_VPAD 132
#define PV_SMEM ((128*PV_PPAD + 64*PV_VPAD + 256)*4)   // 102,400 B

__global__ __launch_bounds__(256)
void pv_kernel(float* __restrict__ attn, const float* __restrict__ Vp,
               float* __restrict__ ctx)
{
  extern __shared__ float sm[];
  float*  Ps   = sm;                         // [128][132] tf32(P chunk)
  float*  Vt   = sm + 128*PV_PPAD;           // [64][132]  tf32(V chunk transposed: [n][k])
  float2* rst  = (float2*)(sm + 128*PV_PPAD + 64*PV_VPAD);   // [128] (M, invS)
  const int tid = threadIdx.x, lane = tid & 31, wid = tid >> 5;
  const int bh = blockIdx.y, b = bh >> 4, h = bh & 15;
  const int bm0 = blockIdx.x * 128;
  const int qg = lane >> 3, lr = lane & 7;
  const int aRow  = wid*16 + (qg & 1)*8 + lr;    // warp owns 16 q-rows
  const int aCol  = (qg >> 1)*4;
  const int bRowV = (qg >> 1)*8 + lr;            // + np*16, over 64 n-rows of Vt
  const int bColV = (qg & 1)*4;

  if (tid < 128) rst[tid] = g_rowstat[(size_t)bh*SEQ + bm0 + tid];

  float* Pbase = attn + (size_t)bh*SEQ*SEQ + (size_t)bm0*SEQ;

  float acc[8][4];
  #pragma unroll
  for (int nt = 0; nt < 8; nt++)
    #pragma unroll
    for (int j = 0; j < 4; j++) acc[nt][j] = 0.f;

  // V transpose-fill mapping: warp w covers k in [32*(w>>1), +32), n-half (w&1)
  const int vk0 = (wid >> 1) * 32;
  const int vn  = (wid & 1) * 32 + lane;
  const float* Vcol = Vp + (size_t)(b*SEQ)*D_MODEL + h*DKH + vn;

  uint32_t psb = smem_u32(Ps), vtb = smem_u32(Vt);
  __syncthreads();                            // rst visible

  for (int ch = 0; ch < 8; ch++) {
    if (ch > 0) __syncthreads();
    // ---- P chunk: read raw S, normalize, write attn in place, tf32 -> smem ----
    #pragma unroll
    for (int i = 0; i < 16; i++) {
      int f4 = i*256 + tid; int r = f4 >> 5; int c = (f4 & 31) << 2;
      float* gp = Pbase + (size_t)r*SEQ + ch*128 + c;
      float4 s4 = *(const float4*)gp;
      float2 ms = rst[r];
      float4 p4;
      p4.x = fast_exp(s4.x - ms.x) * ms.y;
      p4.y = fast_exp(s4.y - ms.x) * ms.y;
      p4.z = fast_exp(s4.z - ms.x) * ms.y;
      p4.w = fast_exp(s4.w - ms.x) * ms.y;
      *(float4*)gp = p4;                       // final attention output
      uint4 u; u.x=f2tf32(p4.x); u.y=f2tf32(p4.y); u.z=f2tf32(p4.z); u.w=f2tf32(p4.w);
      *(uint4*)(Ps + r*PV_PPAD + c) = u;
    }
    // ---- V chunk transposed: Vt[n][k] ----
    {
      const float* vb = Vcol + (size_t)(ch*128 + vk0)*D_MODEL;
      #pragma unroll
      for (int g8 = 0; g8 < 8; g8++) {
        uint4 u;
        u.x = f2tf32(vb[(size_t)(g8*4+0)*D_MODEL]);
        u.y = f2tf32(vb[(size_t)(g8*4+1)*D_MODEL]);
        u.z = f2tf32(vb[(size_t)(g8*4+2)*D_MODEL]);
        u.w = f2tf32(vb[(size_t)(g8*4+3)*D_MODEL]);
        *(uint4*)(Vt + vn*PV_VPAD + vk0 + g8*4) = u;
      }
    }
    __syncthreads();
    #pragma unroll
    for (int kk = 0; kk < 16; kk++) {
      unsigned a0,a1,a2,a3;
      ldsm4(a0,a1,a2,a3, psb + ((unsigned)(aRow*PV_PPAD + aCol + kk*8) << 2));
      unsigned bf[8][2];
      #pragma unroll
      for (int np = 0; np < 4; np++) {
        unsigned r0,r1,r2,r3;
        ldsm4(r0,r1,r2,r3, vtb + ((unsigned)((bRowV + np*16)*PV_VPAD + bColV + kk*8) << 2));
        bf[2*np][0]=r0; bf[2*np][1]=r1; bf[2*np+1][0]=r2; bf[2*np+1][1]=r3;
      }
      #pragma unroll
      for (int nt = 0; nt < 8; nt++)
        mma_tf32(acc[nt][0], acc[nt][1], acc[nt][2], acc[nt][3], a0,a1,a2,a3, bf[nt][0], bf[nt][1]);
    }
  }

  const int q = bm0 + wid*16 + (lane >> 2);
  #pragma unroll
  for (int nt = 0; nt < 8; nt++) {
    int c = h*DKH + nt*8 + (lane & 3)*2;
    *(float2*)(ctx + (size_t)(b*SEQ + q)*D_MODEL + c)     = make_float2(acc[nt][0], acc[nt][1]);
    *(float2*)(ctx + (size_t)(b*SEQ + q + 8)*D_MODEL + c) = make_float2(acc[nt][2], acc[nt][3]);
  }
}

// ================= launch =================
extern "C" void kernel_launch(void* const* d_in, const int* in_sizes, int n_in,
                              void* d_out, int out_size)
{
  const float* q  = (const float*)d_in[0];
  const float* k  = (const float*)d_in[1];
  const float* v  = (const float*)d_in[2];
  const float* Wq = (const float*)d_in[3];
  const float* bq = (const float*)d_in[4];
  const float* Wk = (const float*)d_in[5];
  const float* bk = (const float*)d_in[6];
  const float* Wv = (const float*)d_in[7];
  const float* bv = (const float*)d_in[8];
  const float* Wo = (const float*)d_in[9];
  const float* bo = (const float*)d_in[10];

  float* out  = (float*)d_out;                 // (out, attention) concatenated
  float* attn = out + OUT_ELEMS;

  void *pq, *pk, *pv, *pctx;
  cudaGetSymbolAddress(&pq,   g_q);
  cudaGetSymbolAddress(&pk,   g_k);
  cudaGetSymbolAddress(&pv,   g_v);
  cudaGetSymbolAddress(&pctx, g_ctx);

  cudaFuncSetAttribute(gemm_tf32_kernel, cudaFuncAttributeMaxDynamicSharedMemorySize, GEMM_SMEM_BYTES);
  cudaFuncSetAttribute(qkv_gemm_kernel,  cudaFuncAttributeMaxDynamicSharedMemorySize, GEMM_SMEM_BYTES);
  cudaFuncSetAttribute(scores_kernel,    cudaFuncAttributeMaxDynamicSharedMemorySize, SC_SMEM);
  cudaFuncSetAttribute(pv_kernel,        cudaFuncAttributeMaxDynamicSharedMemorySize, PV_SMEM);

  dim3 gq(D_MODEL/GBN, MROWS/GBM, 3);          // (8, 64, 3) fused QKV
  qkv_gemm_kernel<<<gq, 256, GEMM_SMEM_BYTES>>>(q, k, v, Wq, Wk, Wv, bq, bk, bv,
                                                (float*)pq, (float*)pk, (float*)pv);

  dim3 gs(SEQ/128, SEQ/128, BATCH*NHEAD);      // (8, 8, 128)
  scores_kernel<<<gs, 256, SC_SMEM>>>((const float*)pq, (const float*)pk, attn);

  combine_kernel<<<NROWS_TOT/256, 256>>>();

  dim3 gp(SEQ/128, BATCH*NHEAD);               // (8, 128)
  pv_kernel<<<gp, 256, PV_SMEM>>>(attn, (const float*)pv, (float*)pctx);

  dim3 gg(D_MODEL/GBN, MROWS/GBM);             // (8, 64)
  gemm_tf32_kernel<<<gg, 256, GEMM_SMEM_BYTES>>>((const float*)pctx, Wo, bo, out);
}

// round 8
// speedup vs baseline: 2.3842x; 1.1638x over previous
#include <cuda_runtime.h>
#include <cstdint>

#define D_MODEL 1024
#define NHEAD   16
#define DKH     64
#define BATCH   8
#define SEQ     1024
#define MROWS   (BATCH*SEQ)                   // 8192
#define OUT_ELEMS  (MROWS*D_MODEL)            // 8388608
#define ATTN_ELEMS (BATCH*NHEAD*SEQ*SEQ)      // 134217728
#define NROWS_TOT  (BATCH*NHEAD*SEQ)          // 131072 attention rows

// ---------------- scratch (no cudaMalloc allowed) ----------------
__device__ float g_q  [MROWS*D_MODEL];
__device__ float g_k  [MROWS*D_MODEL];
__device__ float g_v  [MROWS*D_MODEL];
__device__ float g_ctx[MROWS*D_MODEL];
__device__ float g_statm[NROWS_TOT*8];        // per (row, bn-tile) max
__device__ float g_stats[NROWS_TOT*8];        // per (row, bn-tile) sum-exp
__device__ float2 g_rowstat[NROWS_TOT];       // per row (M, 1/S)

// ---------------- helpers ----------------
__device__ __forceinline__ unsigned f2tf32(float f){
  unsigned r; asm("cvt.rna.tf32.f32 %0, %1;" : "=r"(r) : "f"(f)); return r;
}
__device__ __forceinline__ uint32_t smem_u32(const void* p){
  return (uint32_t)__cvta_generic_to_shared(p);
}
__device__ __forceinline__ void ldsm4(unsigned &r0, unsigned &r1, unsigned &r2, unsigned &r3, uint32_t a){
  asm volatile("ldmatrix.sync.aligned.m8n8.x4.shared.b16 {%0,%1,%2,%3}, [%4];"
    : "=r"(r0),"=r"(r1),"=r"(r2),"=r"(r3) : "r"(a));
}
__device__ __forceinline__ void mma_tf32(float &d0,float &d1,float &d2,float &d3,
    unsigned a0,unsigned a1,unsigned a2,unsigned a3, unsigned b0,unsigned b1){
  asm volatile("mma.sync.aligned.m16n8k8.row.col.f32.tf32.tf32.f32 "
    "{%0,%1,%2,%3}, {%4,%5,%6,%7}, {%8,%9}, {%0,%1,%2,%3};"
    : "+f"(d0),"+f"(d1),"+f"(d2),"+f"(d3)
    : "r"(a0),"r"(a1),"r"(a2),"r"(a3),"r"(b0),"r"(b1));
}
// FFMA-only exp (avoids MUFU rt=8 for 134M exps). Valid for x <= 0 after max-sub.
__device__ __forceinline__ float fast_exp(float x){
  x = fmaxf(x, -80.f);
  float z  = fmaf(x, 1.4426950408889634f, 12582912.f);
  int   n  = __float_as_int(z) - 0x4B400000;
  float fn = z - 12582912.f;
  float t  = fmaf(x, 1.4426950408889634f, -fn);
  float u  = t * 0.6931471805599453f;
  float p  = fmaf(u, 0.0083333333f, 0.0416666667f);
  p = fmaf(u, p, 0.1666666667f);
  p = fmaf(u, p, 0.5f);
  p = fmaf(u, p, 1.0f);
  p = fmaf(u, p, 1.0f);
  return __int_as_float((n + 127) << 23) * p;
}

// ================= TF32 GEMM body:  C[8192,1024] = A @ W^T + bias =================
#define GBM 128
#define GBN 128
#define GBK 32
#define GPAD 36
#define GEMM_SMEM_BYTES (4*GBM*GPAD*4)
#define GK 1024
#define GN 1024

__device__ __forceinline__ void gemm_body(const float* __restrict__ A,
                                          const float* __restrict__ W,
                                          const float* __restrict__ bias,
                                          float* __restrict__ C, float* sm)
{
  float* As = sm;
  float* Ws = sm + 2*GBM*GPAD;
  const int tid = threadIdx.x, lane = tid & 31, wid = tid >> 5;
  const int wr = wid & 3, wc = wid >> 2;
  const int bm0 = blockIdx.y * GBM, bn0 = blockIdx.x * GBN;
  const int qg = lane >> 3, lr = lane & 7;
  const int aRow = wr*32 + (qg & 1)*8 + lr;
  const int aCol = (qg >> 1)*4;
  const int bRow = wc*64 + (qg >> 1)*8 + lr;
  const int bCol = (qg & 1)*4;

  float acc[2][8][4];
  #pragma unroll
  for (int mt = 0; mt < 2; mt++)
    #pragma unroll
    for (int nt = 0; nt < 8; nt++)
      #pragma unroll
      for (int j = 0; j < 4; j++) acc[mt][nt][j] = 0.f;

  float4 ra[4], rw[4];
  const int nT = GK / GBK;

  #pragma unroll
  for (int i = 0; i < 4; i++) {
    int f4 = i*256 + tid; int r = f4 >> 3; int c = (f4 & 7) << 2;
    ra[i] = *(const float4*)(A + (size_t)(bm0 + r)*GK + c);
    rw[i] = *(const float4*)(W + (size_t)(bn0 + r)*GK + c);
  }

  for (int t = 0; t < nT; t++) {
    float* as = As + (t & 1)*GBM*GPAD;
    float* ws = Ws + (t & 1)*GBM*GPAD;
    #pragma unroll
    for (int i = 0; i < 4; i++) {
      int f4 = i*256 + tid; int r = f4 >> 3; int c = (f4 & 7) << 2;
      uint4 ua; ua.x=f2tf32(ra[i].x); ua.y=f2tf32(ra[i].y); ua.z=f2tf32(ra[i].z); ua.w=f2tf32(ra[i].w);
      uint4 uw; uw.x=f2tf32(rw[i].x); uw.y=f2tf32(rw[i].y); uw.z=f2tf32(rw[i].z); uw.w=f2tf32(rw[i].w);
      *(uint4*)(as + r*GPAD + c) = ua;
      *(uint4*)(ws + r*GPAD + c) = uw;
    }
    __syncthreads();
    if (t + 1 < nT) {
      int k0 = (t + 1)*GBK;
      #pragma unroll
      for (int i = 0; i < 4; i++) {
        int f4 = i*256 + tid; int r = f4 >> 3; int c = (f4 & 7) << 2;
        ra[i] = *(const float4*)(A + (size_t)(bm0 + r)*GK + k0 + c);
        rw[i] = *(const float4*)(W + (size_t)(bn0 + r)*GK + k0 + c);
      }
    }
    uint32_t asb = smem_u32(as), wsb = smem_u32(ws);
    #pragma unroll
    for (int kk = 0; kk < 4; kk++) {
      unsigned af[2][4];
      #pragma unroll
      for (int mt = 0; mt < 2; mt++)
        ldsm4(af[mt][0], af[mt][1], af[mt][2], af[mt][3],
              asb + ((unsigned)((aRow + mt*16)*GPAD + aCol + kk*8) << 2));
      unsigned bf[8][2];
      #pragma unroll
      for (int np = 0; np < 4; np++) {
        unsigned r0, r1, r2, r3;
        ldsm4(r0, r1, r2, r3, wsb + ((unsigned)((bRow + np*16)*GPAD + bCol + kk*8) << 2));
        bf[2*np][0]=r0; bf[2*np][1]=r1; bf[2*np+1][0]=r2; bf[2*np+1][1]=r3;
      }
      #pragma unroll
      for (int mt = 0; mt < 2; mt++)
        #pragma unroll
        for (int nt = 0; nt < 8; nt++)
          mma_tf32(acc[mt][nt][0], acc[mt][nt][1], acc[mt][nt][2], acc[mt][nt][3],
                   af[mt][0], af[mt][1], af[mt][2], af[mt][3], bf[nt][0], bf[nt][1]);
    }
  }

  #pragma unroll
  for (int mt = 0; mt < 2; mt++)
    #pragma unroll
    for (int nt = 0; nt < 8; nt++) {
      int r = bm0 + wr*32 + mt*16 + (lane >> 2);
      int c = bn0 + wc*64 + nt*8 + (lane & 3)*2;
      float2 bb = *(const float2*)(bias + c);
      float2 v0 = make_float2(acc[mt][nt][0] + bb.x, acc[mt][nt][1] + bb.y);
      float2 v1 = make_float2(acc[mt][nt][2] + bb.x, acc[mt][nt][3] + bb.y);
      *(float2*)(C + (size_t)r*GN + c)       = v0;
      *(float2*)(C + (size_t)(r + 8)*GN + c) = v1;
    }
}

__global__ __launch_bounds__(256)
void gemm_tf32_kernel(const float* __restrict__ A, const float* __restrict__ W,
                      const float* __restrict__ bias, float* __restrict__ C)
{
  extern __shared__ float sm[];
  gemm_body(A, W, bias, C, sm);
}

// QKV fused: blockIdx.z selects which projection.
__global__ __launch_bounds__(256)
void qkv_gemm_kernel(const float* __restrict__ q, const float* __restrict__ k,
                     const float* __restrict__ v,
                     const float* __restrict__ Wq, const float* __restrict__ Wk,
                     const float* __restrict__ Wv,
                     const float* __restrict__ bq, const float* __restrict__ bk,
                     const float* __restrict__ bv,
                     float* __restrict__ Cq, float* __restrict__ Ck, float* __restrict__ Cv)
{
  extern __shared__ float sm[];
  const float *A, *W, *bias; float* C;
  if (blockIdx.z == 0)      { A = q; W = Wq; bias = bq; C = Cq; }
  else if (blockIdx.z == 1) { A = k; W = Wk; bias = bk; C = Ck; }
  else                      { A = v; W = Wv; bias = bv; C = Cv; }
  gemm_body(A, W, bias, C, sm);
}

// ======== stats: per-tile row stats of S = (Q/8 @ K^T); NO raw-score write ========
#define SC_PAD 68
#define SC_SMEM (2*128*SC_PAD*4)     // 69632 B

__global__ __launch_bounds__(256)
void stats_kernel(const float* __restrict__ Qp, const float* __restrict__ Kp)
{
  extern __shared__ float sm[];
  float* As = sm;                    // [128][68] q-rows (pre-scaled 1/8), tf32
  float* Bs = sm + 128*SC_PAD;       // [128][68] k-rows, tf32
  const int tid = threadIdx.x, lane = tid & 31, wid = tid >> 5;
  const int wr = wid & 3, wc = wid >> 2;
  const int bh = blockIdx.z, b = bh >> 4, h = bh & 15;
  const int bm0 = blockIdx.y * 128, bn0 = blockIdx.x * 128;
  const int qg = lane >> 3, lr = lane & 7;
  const int aRow = wr*32 + (qg & 1)*8 + lr;
  const int aCol = (qg >> 1)*4;
  const int bRow = wc*64 + (qg >> 1)*8 + lr;
  const int bCol = (qg & 1)*4;

  #pragma unroll
  for (int i = 0; i < 8; i++) {
    int f4 = i*256 + tid; int r = f4 >> 4; int c = (f4 & 15) << 2;
    float4 va = *(const float4*)(Qp + (size_t)(b*SEQ + bm0 + r)*D_MODEL + h*DKH + c);
    float4 vb = *(const float4*)(Kp + (size_t)(b*SEQ + bn0 + r)*D_MODEL + h*DKH + c);
    uint4 ua; ua.x=f2tf32(0.125f*va.x); ua.y=f2tf32(0.125f*va.y);
              ua.z=f2tf32(0.125f*va.z); ua.w=f2tf32(0.125f*va.w);
    uint4 ub; ub.x=f2tf32(vb.x); ub.y=f2tf32(vb.y); ub.z=f2tf32(vb.z); ub.w=f2tf32(vb.w);
    *(uint4*)(As + r*SC_PAD + c) = ua;
    *(uint4*)(Bs + r*SC_PAD + c) = ub;
  }
  __syncthreads();

  float acc[2][8][4];
  #pragma unroll
  for (int mt = 0; mt < 2; mt++)
    #pragma unroll
    for (int nt = 0; nt < 8; nt++)
      #pragma unroll
      for (int j = 0; j < 4; j++) acc[mt][nt][j] = 0.f;

  uint32_t asb = smem_u32(As), bsb = smem_u32(Bs);
  #pragma unroll
  for (int kk = 0; kk < 8; kk++) {
    unsigned af[2][4];
    #pragma unroll
    for (int mt = 0; mt < 2; mt++)
      ldsm4(af[mt][0], af[mt][1], af[mt][2], af[mt][3],
            asb + ((unsigned)((aRow + mt*16)*SC_PAD + aCol + kk*8) << 2));
    unsigned bf[8][2];
    #pragma unroll
    for (int np = 0; np < 4; np++) {
      unsigned r0, r1, r2, r3;
      ldsm4(r0, r1, r2, r3, bsb + ((unsigned)((bRow + np*16)*SC_PAD + bCol + kk*8) << 2));
      bf[2*np][0]=r0; bf[2*np][1]=r1; bf[2*np+1][0]=r2; bf[2*np+1][1]=r3;
    }
    #pragma unroll
    for (int mt = 0; mt < 2; mt++)
      #pragma unroll
      for (int nt = 0; nt < 8; nt++)
        mma_tf32(acc[mt][nt][0], acc[mt][nt][1], acc[mt][nt][2], acc[mt][nt][3],
                 af[mt][0], af[mt][1], af[mt][2], af[mt][3], bf[nt][0], bf[nt][1]);
  }

  // ---- per-tile row stats: m = max over 128 cols, sigma = sum exp(s - m) ----
  __syncthreads();                   // done with As/Bs smem -> reuse
  float* mp = sm;                    // [2][128] per-wc row max
  float* sp = sm + 256;              // [2][128] per-wc row sumexp
  #pragma unroll
  for (int mt = 0; mt < 2; mt++)
    #pragma unroll
    for (int hh = 0; hh < 2; hh++) {
      float m = -1e30f;
      #pragma unroll
      for (int nt = 0; nt < 8; nt++)
        m = fmaxf(m, fmaxf(acc[mt][nt][2*hh], acc[mt][nt][2*hh+1]));
      #pragma unroll
      for (int off = 1; off <= 2; off <<= 1)
        m = fmaxf(m, __shfl_xor_sync(0xffffffffu, m, off));
      if ((lane & 3) == 0)
        mp[wc*128 + wr*32 + mt*16 + hh*8 + (lane >> 2)] = m;
    }
  __syncthreads();
  #pragma unroll
  for (int mt = 0; mt < 2; mt++)
    #pragma unroll
    for (int hh = 0; hh < 2; hh++) {
      int rl = wr*32 + mt*16 + hh*8 + (lane >> 2);
      float m = fmaxf(mp[rl], mp[128 + rl]);
      float s = 0.f;
      #pragma unroll
      for (int nt = 0; nt < 8; nt++)
        s += fast_exp(acc[mt][nt][2*hh] - m) + fast_exp(acc[mt][nt][2*hh+1] - m);
      #pragma unroll
      for (int off = 1; off <= 2; off <<= 1)
        s += __shfl_xor_sync(0xffffffffu, s, off);
      if ((lane & 3) == 0) sp[wc*128 + rl] = s;
    }
  __syncthreads();
  if (tid < 128) {
    float m = fmaxf(mp[tid], mp[128 + tid]);
    float s = sp[tid] + sp[128 + tid];
    size_t idx = ((size_t)(bh*SEQ + bm0 + tid))*8 + blockIdx.x;
    g_statm[idx] = m;
    g_stats[idx] = s;
  }
}

// ======== combine: per row M = max_t m_t, S = sum_t exp(m_t - M) * sigma_t ========
__global__ __launch_bounds__(256)
void combine_kernel()
{
  int g = blockIdx.x*256 + threadIdx.x;     // 131072 rows
  const float* mrow = g_statm + (size_t)g*8;
  const float* srow = g_stats + (size_t)g*8;
  float M = -1e30f;
  #pragma unroll
  for (int t = 0; t < 8; t++) M = fmaxf(M, mrow[t]);
  float S = 0.f;
  #pragma unroll
  for (int t = 0; t < 8; t++) S += fast_exp(mrow[t] - M) * srow[t];
  g_rowstat[g] = make_float2(M, 1.f / S);
}

// ======== fused apv: recompute S chunk, normalize, write attn ONCE, PV accumulate ========
// CTA = (128 q-rows, bh). 16 chunks of 64 K-columns.
#define AP_PAD 68
#define AP_Q   0                          // [128][68] Q tf32 (pre-scaled 1/8)
#define AP_K   (128*AP_PAD)               // [64][68]  K chunk tf32
#define AP_V   (AP_K + 64*AP_PAD)         // [64][68]  V chunk transposed [n][k] tf32
#define AP_P   (AP_V + 64*AP_PAD)         // [128][68] P tf32
#define AP_RST (AP_P + 128*AP_PAD)        // [128] float2
#define APV_SMEM ((AP_RST + 256)*4)       // 105,472 B

__global__ void __launch_bounds__(256, 2)
apv_kernel(const float* __restrict__ Qp, const float* __restrict__ Kp,
           const float* __restrict__ Vp,
           float* __restrict__ attn, float* __restrict__ ctx)
{
  extern __shared__ float sm[];
  float*  Qs  = sm + AP_Q;
  float*  Kc  = sm + AP_K;
  float*  Vt  = sm + AP_V;
  float*  Ps  = sm + AP_P;
  float2* rst = (float2*)(sm + AP_RST);
  const int tid = threadIdx.x, lane = tid & 31, wid = tid >> 5;
  const int bh = blockIdx.y, b = bh >> 4, h = bh & 15;
  const int bm0 = blockIdx.x * 128;
  const int qg = lane >> 3, lr = lane & 7;
  // QK mma mapping: 4x2 warp grid, warp tile 32m x 32n
  const int wr = wid & 3, wc = wid >> 2;
  const int aRowQ = wr*32 + (qg & 1)*8 + lr;
  const int aCol  = (qg >> 1)*4;
  const int bRowK = wc*32 + (qg >> 1)*8 + lr;
  const int bColK = (qg & 1)*4;
  // PV mma mapping: warp owns 16 q-rows, all 64 n
  const int aRowP = wid*16 + (qg & 1)*8 + lr;
  const int bRowV = (qg >> 1)*8 + lr;            // + np*16
  const int bColV = (qg & 1)*4;
  // V transpose-fill: vn = tid&63 (n), vk0 = (tid>>6)*16 (k group)
  const int vn  = tid & 63;
  const int vk0 = (tid >> 6) * 16;

  if (tid < 128) rst[tid] = g_rowstat[(size_t)bh*SEQ + bm0 + tid];

  // Q tile 128x64 -> tf32 smem, pre-scaled 1/8
  #pragma unroll
  for (int i = 0; i < 8; i++) {
    int f4 = i*256 + tid; int r = f4 >> 4; int c = (f4 & 15) << 2;
    float4 v = *(const float4*)(Qp + (size_t)(b*SEQ + bm0 + r)*D_MODEL + h*DKH + c);
    uint4 u; u.x=f2tf32(0.125f*v.x); u.y=f2tf32(0.125f*v.y);
             u.z=f2tf32(0.125f*v.z); u.w=f2tf32(0.125f*v.w);
    *(uint4*)(Qs + r*AP_PAD + c) = u;
  }

  float* Abase = attn + (size_t)bh*SEQ*SEQ + (size_t)bm0*SEQ;
  const float* Vcol = Vp + (size_t)(b*SEQ)*D_MODEL + h*DKH + vn;

  float oacc[8][4];
  #pragma unroll
  for (int nt = 0; nt < 8; nt++)
    #pragma unroll
    for (int j = 0; j < 4; j++) oacc[nt][j] = 0.f;

  uint32_t qsb = smem_u32(Qs), kcb = smem_u32(Kc), vtb = smem_u32(Vt), psb = smem_u32(Ps);

  for (int ch = 0; ch < 16; ch++) {
    __syncthreads();                          // Kc/Vt/Ps free; covers Qs/rst on ch==0
    // ---- K chunk 64x64 -> tf32 smem ----
    #pragma unroll
    for (int i = 0; i < 4; i++) {
      int f4 = i*256 + tid; int r = f4 >> 4; int c = (f4 & 15) << 2;
      float4 v = *(const float4*)(Kp + (size_t)(b*SEQ + ch*64 + r)*D_MODEL + h*DKH + c);
      uint4 u; u.x=f2tf32(v.x); u.y=f2tf32(v.y); u.z=f2tf32(v.z); u.w=f2tf32(v.w);
      *(uint4*)(Kc + r*AP_PAD + c) = u;
    }
    // ---- V chunk transposed: Vt[n][k], k in [vk0, vk0+16) ----
    {
      const float* vb = Vcol + (size_t)(ch*64 + vk0)*D_MODEL;
      #pragma unroll
      for (int g8 = 0; g8 < 4; g8++) {
        uint4 u;
        u.x = f2tf32(vb[(size_t)(g8*4+0)*D_MODEL]);
        u.y = f2tf32(vb[(size_t)(g8*4+1)*D_MODEL]);
        u.z = f2tf32(vb[(size_t)(g8*4+2)*D_MODEL]);
        u.w = f2tf32(vb[(size_t)(g8*4+3)*D_MODEL]);
        *(uint4*)(Vt + vn*AP_PAD + vk0 + g8*4) = u;
      }
    }
    __syncthreads();

    // ---- QK mma: S tile 128x64 (this chunk's columns) ----
    float sacc[2][4][4];
    #pragma unroll
    for (int mt = 0; mt < 2; mt++)
      #pragma unroll
      for (int nt = 0; nt < 4; nt++)
        #pragma unroll
        for (int j = 0; j < 4; j++) sacc[mt][nt][j] = 0.f;
    #pragma unroll
    for (int kk = 0; kk < 8; kk++) {
      unsigned af[2][4];
      #pragma unroll
      for (int mt = 0; mt < 2; mt++)
        ldsm4(af[mt][0], af[mt][1], af[mt][2], af[mt][3],
              qsb + ((unsigned)((aRowQ + mt*16)*AP_PAD + aCol + kk*8) << 2));
      unsigned bf[4][2];
      #pragma unroll
      for (int np = 0; np < 2; np++) {
        unsigned r0, r1, r2, r3;
        ldsm4(r0, r1, r2, r3, kcb + ((unsigned)((bRowK + np*16)*AP_PAD + bColK + kk*8) << 2));
        bf[2*np][0]=r0; bf[2*np][1]=r1; bf[2*np+1][0]=r2; bf[2*np+1][1]=r3;
      }
      #pragma unroll
      for (int mt = 0; mt < 2; mt++)
        #pragma unroll
        for (int nt = 0; nt < 4; nt++)
          mma_tf32(sacc[mt][nt][0], sacc[mt][nt][1], sacc[mt][nt][2], sacc[mt][nt][3],
                   af[mt][0], af[mt][1], af[mt][2], af[mt][3], bf[nt][0], bf[nt][1]);
    }

    // ---- normalize, write final attention, store tf32(P) to smem ----
    #pragma unroll
    for (int mt = 0; mt < 2; mt++) {
      int r0 = wr*32 + mt*16 + (lane >> 2);
      float2 ms0 = rst[r0];
      float2 ms1 = rst[r0 + 8];
      #pragma unroll
      for (int nt = 0; nt < 4; nt++) {
        int c = wc*32 + nt*8 + (lane & 3)*2;
        float p0 = fast_exp(sacc[mt][nt][0] - ms0.x) * ms0.y;
        float p1 = fast_exp(sacc[mt][nt][1] - ms0.x) * ms0.y;
        float p2 = fast_exp(sacc[mt][nt][2] - ms1.x) * ms1.y;
        float p3 = fast_exp(sacc[mt][nt][3] - ms1.x) * ms1.y;
        *(float2*)(Abase + (size_t)r0*SEQ + ch*64 + c)       = make_float2(p0, p1);
        *(float2*)(Abase + (size_t)(r0 + 8)*SEQ + ch*64 + c) = make_float2(p2, p3);
        uint2 u0 = make_uint2(f2tf32(p0), f2tf32(p1));
        uint2 u1 = make_uint2(f2tf32(p2), f2tf32(p3));
        *(uint2*)(Ps + r0*AP_PAD + c)       = u0;
        *(uint2*)(Ps + (r0 + 8)*AP_PAD + c) = u1;
      }
    }
    __syncthreads();                          // Ps ready

    // ---- PV mma accumulate: oacc += P(128x64) @ Vt^T(64x64) ----
    #pragma unroll
    for (int kk = 0; kk < 8; kk++) {
      unsigned a0,a1,a2,a3;
      ldsm4(a0,a1,a2,a3, psb + ((unsigned)(aRowP*AP_PAD + aCol + kk*8) << 2));
      unsigned bf[8][2];
      #pragma unroll
      for (int np = 0; np < 4; np++) {
        unsigned r0,r1,r2,r3;
        ldsm4(r0,r1,r2,r3, vtb + ((unsigned)((bRowV + np*16)*AP_PAD + bColV + kk*8) << 2));
        bf[2*np][0]=r0; bf[2*np][1]=r1; bf[2*np+1][0]=r2; bf[2*np+1][1]=r3;
      }
      #pragma unroll
      for (int nt = 0; nt < 8; nt++)
        mma_tf32(oacc[nt][0], oacc[nt][1], oacc[nt][2], oacc[nt][3], a0,a1,a2,a3, bf[nt][0], bf[nt][1]);
    }
  }

  const int q = bm0 + wid*16 + (lane >> 2);
  #pragma unroll
  for (int nt = 0; nt < 8; nt++) {
    int c = h*DKH + nt*8 + (lane & 3)*2;
    *(float2*)(ctx + (size_t)(b*SEQ + q)*D_MODEL + c)     = make_float2(oacc[nt][0], oacc[nt][1]);
    *(float2*)(ctx + (size_t)(b*SEQ + q + 8)*D_MODEL + c) = make_float2(oacc[nt][2], oacc[nt][3]);
  }
}

// ================= launch =================
extern "C" void kernel_launch(void* const* d_in, const int* in_sizes, int n_in,
                              void* d_out, int out_size)
{
  const float* q  = (const float*)d_in[0];
  const float* k  = (const float*)d_in[1];
  const float* v  = (const float*)d_in[2];
  const float* Wq = (const float*)d_in[3];
  const float* bq = (const float*)d_in[4];
  const float* Wk = (const float*)d_in[5];
  const float* bk = (const float*)d_in[6];
  const float* Wv = (const float*)d_in[7];
  const float* bv = (const float*)d_in[8];
  const float* Wo = (const float*)d_in[9];
  const float* bo = (const float*)d_in[10];

  float* out  = (float*)d_out;                 // (out, attention) concatenated
  float* attn = out + OUT_ELEMS;

  void *pq, *pk, *pv, *pctx;
  cudaGetSymbolAddress(&pq,   g_q);
  cudaGetSymbolAddress(&pk,   g_k);
  cudaGetSymbolAddress(&pv,   g_v);
  cudaGetSymbolAddress(&pctx, g_ctx);

  cudaFuncSetAttribute(gemm_tf32_kernel, cudaFuncAttributeMaxDynamicSharedMemorySize, GEMM_SMEM_BYTES);
  cudaFuncSetAttribute(qkv_gemm_kernel,  cudaFuncAttributeMaxDynamicSharedMemorySize, GEMM_SMEM_BYTES);
  cudaFuncSetAttribute(stats_kernel,     cudaFuncAttributeMaxDynamicSharedMemorySize, SC_SMEM);
  cudaFuncSetAttribute(apv_kernel,       cudaFuncAttributeMaxDynamicSharedMemorySize, APV_SMEM);

  dim3 gq(D_MODEL/GBN, MROWS/GBM, 3);          // (8, 64, 3) fused QKV
  qkv_gemm_kernel<<<gq, 256, GEMM_SMEM_BYTES>>>(q, k, v, Wq, Wk, Wv, bq, bk, bv,
                                                (float*)pq, (float*)pk, (float*)pv);

  dim3 gs(SEQ/128, SEQ/128, BATCH*NHEAD);      // (8, 8, 128)
  stats_kernel<<<gs, 256, SC_SMEM>>>((const float*)pq, (const float*)pk);

  combine_kernel<<<NROWS_TOT/256, 256>>>();

  dim3 gp(SEQ/128, BATCH*NHEAD);               // (8, 128)
  apv_kernel<<<gp, 256, APV_SMEM>>>((const float*)pq, (const float*)pk, (const float*)pv,
                                    attn, (float*)pctx);

  dim3 gg(D_MODEL/GBN, MROWS/GBM);             // (8, 64)
  gemm_tf32_kernel<<<gg, 256, GEMM_SMEM_BYTES>>>((const float*)pctx, Wo, bo, out);
}